// round 5
// baseline (speedup 1.0000x reference)
#include <cuda_runtime.h>
#include <cuda_fp16.h>

#define N_NODES 50000
#define N_EDGES 800000
#define D_FEAT  128

// ---- device-global scratch (no runtime allocation allowed) ----
__device__ int g_row_ptr[N_NODES + 1];
// x quantized to fp16: 50000*128 halves = 12.8 MB, stored as uint4 (8 halves)
__device__ uint4 g_x_half[(size_t)N_NODES * D_FEAT / 8];   // exactly N_EDGES entries
// packed edge metadata: .x = col, .y = val as replicated half2 bits
__device__ uint2 g_meta[N_EDGES];

// ---- fused prologue: one thread per edge does 3 small jobs ----
// (N_NODES*D_FEAT/8 == N_EDGES == 800000, so one grid covers all three.)
__global__ __launch_bounds__(256)
void prologue_kernel(const float* __restrict__ x,
                     const float* __restrict__ vals,
                     const int* __restrict__ rows,
                     const int* __restrict__ cols) {
    int t = blockIdx.x * blockDim.x + threadIdx.x;
    if (t >= N_EDGES) return;

    // 1) x -> fp16: t-th uint4 covers floats [8t, 8t+8)
    {
        const float4* __restrict__ x4 = (const float4*)x;
        float4 a = x4[2 * t + 0];
        float4 b = x4[2 * t + 1];
        __half2 h0 = __floats2half2_rn(a.x, a.y);
        __half2 h1 = __floats2half2_rn(a.z, a.w);
        __half2 h2 = __floats2half2_rn(b.x, b.y);
        __half2 h3 = __floats2half2_rn(b.z, b.w);
        uint4 o;
        o.x = *(unsigned int*)&h0; o.y = *(unsigned int*)&h1;
        o.z = *(unsigned int*)&h2; o.w = *(unsigned int*)&h3;
        g_x_half[t] = o;
    }

    // 2) packed metadata (col, replicated half2 val)
    {
        __half  hv = __float2half_rn(vals[t]);
        __half2 v2 = __half2half2(hv);
        uint2 m;
        m.x = (unsigned int)cols[t];
        m.y = *(unsigned int*)&v2;
        g_meta[t] = m;
    }

    // 3) CSR row_ptr from sorted COO rows
    {
        int r = rows[t];
        int rprev = (t == 0) ? -1 : rows[t - 1];
        for (int q = rprev + 1; q <= r; q++) g_row_ptr[q] = t;
        if (t == N_EDGES - 1) {
            for (int q = r + 1; q <= N_NODES; q++) g_row_ptr[q] = N_EDGES;
        }
    }
}

// ---- main: warp per row, paired-edge fp16 gather, HFMA2, fp32 flush ----
// Lanes 0-15 serve even edges, 16-31 odd edges. Each lane loads one uint4
// (8 halves) per step; accumulates in half2 for at most 8 edges (4 steps),
// then flushes into fp32 accumulators. Atomic-free (rows sorted).
// __launch_bounds__(256, 8): cap regs at 32 -> 64 resident warps/SM to cover
// the ~250-cycle gather scoreboard stalls (R4 was occ=66%, issue=45%).
__global__ __launch_bounds__(256, 8)
void spmm_coo_kernel(float* __restrict__ out) {
    int warp = (blockIdx.x * blockDim.x + threadIdx.x) >> 5;
    int lane = threadIdx.x & 31;
    if (warp >= N_NODES) return;

    int start = g_row_ptr[warp];
    int end   = g_row_ptr[warp + 1];

    int half = lane >> 4;        // 0: even edges, 1: odd edges
    int sub  = lane & 15;        // owns halves [8*sub, 8*sub+8)

    float acc[8];
    #pragma unroll
    for (int k = 0; k < 8; k++) acc[k] = 0.f;

    for (int base = start; base < end; base += 32) {
        int n = end - base;
        if (n > 32) n = 32;

        // One coalesced LDG.64 of packed (col, val_h2); masked lanes hold
        // exact zeros (c=0 -> harmless x[0] gather, vh=0 -> contributes 0).
        uint2 meta = make_uint2(0u, 0u);
        if (lane < n) meta = g_meta[base + lane];

        int nsub = (n + 7) >> 3;              // 1..4 sub-blocks of 8 edges
        for (int b = 0; b < nsub; b++) {
            __half2 a0 = __half2half2(__ushort_as_half(0));
            __half2 a1 = a0, a2 = a0, a3 = a0;

            #pragma unroll
            for (int s = 0; s < 4; s++) {
                int j = b * 8 + s * 2 + half;           // <= 31 always
                unsigned int cj = __shfl_sync(0xffffffffu, meta.x, j);
                unsigned int vj = __shfl_sync(0xffffffffu, meta.y, j);
                __half2 v2 = *(__half2*)&vj;
                uint4 h = g_x_half[(size_t)cj * (D_FEAT / 8) + sub];
                a0 = __hfma2(*(__half2*)&h.x, v2, a0);
                a1 = __hfma2(*(__half2*)&h.y, v2, a1);
                a2 = __hfma2(*(__half2*)&h.z, v2, a2);
                a3 = __hfma2(*(__half2*)&h.w, v2, a3);
            }

            // Flush half2 partials (depth <= 8) into fp32 accumulators.
            float2 f0 = __half22float2(a0);
            float2 f1 = __half22float2(a1);
            float2 f2 = __half22float2(a2);
            float2 f3 = __half22float2(a3);
            acc[0] += f0.x; acc[1] += f0.y;
            acc[2] += f1.x; acc[3] += f1.y;
            acc[4] += f2.x; acc[5] += f2.y;
            acc[6] += f3.x; acc[7] += f3.y;
        }
    }

    // Fold even/odd edge partials: lanes l and l^16 hold the same features.
    #pragma unroll
    for (int k = 0; k < 8; k++)
        acc[k] += __shfl_xor_sync(0xffffffffu, acc[k], 16);

    // Each lane stores one float4: half 0 -> low quad, half 1 -> high quad.
    float4 st;
    if (half == 0) st = make_float4(acc[0], acc[1], acc[2], acc[3]);
    else           st = make_float4(acc[4], acc[5], acc[6], acc[7]);
    ((float4*)out)[(size_t)warp * (D_FEAT / 4) + 2 * sub + half] = st;
}

extern "C" void kernel_launch(void* const* d_in, const int* in_sizes, int n_in,
                              void* d_out, int out_size) {
    const float* x    = (const float*)d_in[0];
    const float* vals = (const float*)d_in[1];
    const int*   rows = (const int*)d_in[2];
    const int*   cols = (const int*)d_in[3];
    float*       out  = (float*)d_out;

    (void)in_sizes; (void)n_in; (void)out_size;

    // 1) Fused prologue: x->fp16, (col,val)->uint2, row_ptr
    {
        int threads = 256;
        int blocks  = (N_EDGES + threads - 1) / threads;
        prologue_kernel<<<blocks, threads>>>(x, vals, rows, cols);
    }

    // 2) Warp-per-row SpMM
    {
        int threads = 256;  // 8 warps/block
        int blocks  = (N_NODES * 32 + threads - 1) / threads;
        spmm_coo_kernel<<<blocks, threads>>>(out);
    }
}

// round 7
// speedup vs baseline: 1.2062x; 1.2062x over previous
#include <cuda_runtime.h>
#include <cuda_fp16.h>

#define N_NODES 50000
#define N_EDGES 800000
#define D_FEAT  128

// ---- device-global scratch (no runtime allocation allowed) ----
__device__ int g_row_ptr[N_NODES + 1];
// x quantized to fp16: 50000*128 halves = 12.8 MB, stored as uint4 (8 halves)
__device__ uint4 g_x_half[(size_t)N_NODES * D_FEAT / 8];   // exactly N_EDGES entries
// packed edge metadata: col (high 16 bits, col<50000<65536) | val fp16 (low 16)
__device__ unsigned int g_meta[N_EDGES];

// ---- fused prologue: one thread per edge does 3 small jobs ----
__global__ __launch_bounds__(256)
void prologue_kernel(const float* __restrict__ x,
                     const float* __restrict__ vals,
                     const int* __restrict__ rows,
                     const int* __restrict__ cols) {
    int t = blockIdx.x * blockDim.x + threadIdx.x;
    if (t >= N_EDGES) return;

    // 1) x -> fp16: t-th uint4 covers floats [8t, 8t+8)
    {
        const float4* __restrict__ x4 = (const float4*)x;
        float4 a = x4[2 * t + 0];
        float4 b = x4[2 * t + 1];
        __half2 h0 = __floats2half2_rn(a.x, a.y);
        __half2 h1 = __floats2half2_rn(a.z, a.w);
        __half2 h2 = __floats2half2_rn(b.x, b.y);
        __half2 h3 = __floats2half2_rn(b.z, b.w);
        uint4 o;
        o.x = *(unsigned int*)&h0; o.y = *(unsigned int*)&h1;
        o.z = *(unsigned int*)&h2; o.w = *(unsigned int*)&h3;
        g_x_half[t] = o;
    }

    // 2) packed metadata: col<<16 | fp16(val)  (lossless for val)
    {
        __half hv = __float2half_rn(vals[t]);
        unsigned short vb = *(unsigned short*)&hv;
        g_meta[t] = ((unsigned int)cols[t] << 16) | (unsigned int)vb;
    }

    // 3) CSR row_ptr from sorted COO rows
    {
        int r = rows[t];
        int rprev = (t == 0) ? -1 : rows[t - 1];
        for (int q = rprev + 1; q <= r; q++) g_row_ptr[q] = t;
        if (t == N_EDGES - 1) {
            for (int q = r + 1; q <= N_NODES; q++) g_row_ptr[q] = N_EDGES;
        }
    }
}

// One paired-edge step: lanes 0-15 take edge j, lanes 16-31 edge j+1.
// meta==0 (ghost edge) contributes exactly 0 (val=0, col=0 -> x[0] gather).
#define PAIR_STEP(JEVEN)                                                     \
    {                                                                        \
        unsigned int pj = __shfl_sync(0xffffffffu, p, (JEVEN) + half);       \
        unsigned int vb = __byte_perm(pj, pj, 0x1010);  /* val -> half2 */   \
        unsigned int cj = pj >> 16;                                          \
        __half2 v2 = *(__half2*)&vb;                                         \
        uint4 h = g_x_half[(size_t)cj * (D_FEAT / 8) + sub];                 \
        a0 = __hfma2(*(__half2*)&h.x, v2, a0);                               \
        a1 = __hfma2(*(__half2*)&h.y, v2, a1);                               \
        a2 = __hfma2(*(__half2*)&h.z, v2, a2);                               \
        a3 = __hfma2(*(__half2*)&h.w, v2, a3);                               \
    }

#define FLUSH()                                                              \
    {                                                                        \
        float2 f0 = __half22float2(a0);                                      \
        float2 f1 = __half22float2(a1);                                      \
        float2 f2 = __half22float2(a2);                                      \
        float2 f3 = __half22float2(a3);                                      \
        acc[0] += f0.x; acc[1] += f0.y; acc[2] += f1.x; acc[3] += f1.y;      \
        acc[4] += f2.x; acc[5] += f2.y; acc[6] += f3.x; acc[7] += f3.y;      \
        a0 = __half2half2(__ushort_as_half(0)); a1 = a0; a2 = a0; a3 = a0;   \
    }

// ---- main: warp per row, paired-edge fp16 gather, HFMA2, fp32 flush ----
__global__ __launch_bounds__(256, 6)
void spmm_coo_kernel(float* __restrict__ out) {
    int warp = (blockIdx.x * blockDim.x + threadIdx.x) >> 5;
    int lane = threadIdx.x & 31;
    if (warp >= N_NODES) return;

    int start = g_row_ptr[warp];
    int end   = g_row_ptr[warp + 1];

    int half = lane >> 4;        // 0: even edges, 1: odd edges
    int sub  = lane & 15;        // owns halves [8*sub, 8*sub+8)

    float acc[8];
    #pragma unroll
    for (int k = 0; k < 8; k++) acc[k] = 0.f;

    for (int base = start; base < end; base += 32) {
        int n = end - base;
        if (n > 32) n = 32;

        // One coalesced LDG.32 of packed metadata; ghost lanes hold 0.
        unsigned int p = 0;
        if (lane < n) p = g_meta[base + lane];

        __half2 a0 = __half2half2(__ushort_as_half(0));
        __half2 a1 = a0, a2 = a0, a3 = a0;

        // Full 8-edge sub-blocks: no guards, no wasted gathers.
        int full = n >> 3;                 // 0..4
        int j = 0;
        for (int b = 0; b < full; b++) {
            PAIR_STEP(j + 0)
            PAIR_STEP(j + 2)
            PAIR_STEP(j + 4)
            PAIR_STEP(j + 6)
            FLUSH()
            j += 8;
        }

        // Guarded tail (uniform branches): only real pair-steps execute.
        if (j < n) {
            PAIR_STEP(j)
            if (j + 2 < n) PAIR_STEP(j + 2)
            if (j + 4 < n) PAIR_STEP(j + 4)
            if (j + 6 < n) PAIR_STEP(j + 6)
            FLUSH()
        }
    }

    // Fold even/odd edge partials: lanes l and l^16 hold the same features.
    #pragma unroll
    for (int k = 0; k < 8; k++)
        acc[k] += __shfl_xor_sync(0xffffffffu, acc[k], 16);

    // Each lane stores one float4: half 0 -> low quad, half 1 -> high quad.
    float4 st;
    if (half == 0) st = make_float4(acc[0], acc[1], acc[2], acc[3]);
    else           st = make_float4(acc[4], acc[5], acc[6], acc[7]);
    ((float4*)out)[(size_t)warp * (D_FEAT / 4) + 2 * sub + half] = st;
}

extern "C" void kernel_launch(void* const* d_in, const int* in_sizes, int n_in,
                              void* d_out, int out_size) {
    const float* x    = (const float*)d_in[0];
    const float* vals = (const float*)d_in[1];
    const int*   rows = (const int*)d_in[2];
    const int*   cols = (const int*)d_in[3];
    float*       out  = (float*)d_out;

    (void)in_sizes; (void)n_in; (void)out_size;

    // 1) Fused prologue: x->fp16, packed meta, row_ptr
    {
        int threads = 256;
        int blocks  = (N_EDGES + threads - 1) / threads;
        prologue_kernel<<<blocks, threads>>>(x, vals, rows, cols);
    }

    // 2) Warp-per-row SpMM
    {
        int threads = 256;  // 8 warps/block
        int blocks  = (N_NODES * 32 + threads - 1) / threads;
        spmm_coo_kernel<<<blocks, threads>>>(out);
    }
}